// round 16
// baseline (speedup 1.0000x reference)
#include <cuda_runtime.h>
#include <cuda_fp16.h>
#include <cstdint>
#include <cstddef>

#define NN   384
#define DIN  128
#define HID  256
#define HID2 128

// ---------------- scratch (device globals: allocation-free) ----------------
__device__ __half g_H0h[HID * NN];               // H0^T fp16 [h][node]
__device__ __half g_Ah [(size_t)NN * NN * HID];  // relu(P@H0 + corr) fp16 : 75.5 MB
__device__ float  g_t1[NN * HID];                // A^T u, accumulated by k_A epilogue
__device__ float  g_t3[NN * HID];
__device__ float  g_v [NN * NN];
__device__ float  g_S [NN * NN];

// ---------------- helpers ----------------
__device__ __forceinline__ void mma_f16(float* c, const uint32_t* a, const uint32_t* b) {
    asm volatile(
        "mma.sync.aligned.m16n8k16.row.col.f32.f16.f16.f32 "
        "{%0,%1,%2,%3}, {%4,%5,%6,%7}, {%8,%9}, {%0,%1,%2,%3};\n"
        : "+f"(c[0]), "+f"(c[1]), "+f"(c[2]), "+f"(c[3])
        : "r"(a[0]), "r"(a[1]), "r"(a[2]), "r"(a[3]), "r"(b[0]), "r"(b[1]));
}
__device__ __forceinline__ void ldsm_x4(uint32_t* r, uint32_t saddr) {
    asm volatile("ldmatrix.sync.aligned.m8n8.x4.shared.b16 {%0,%1,%2,%3}, [%4];"
                 : "=r"(r[0]), "=r"(r[1]), "=r"(r[2]), "=r"(r[3]) : "r"(saddr));
}
__device__ __forceinline__ uint32_t smem_u32(const void* p) {
    uint32_t a;
    asm("{ .reg .u64 t; cvta.to.shared.u64 t, %1; cvt.u32.u64 %0, t; }" : "=r"(a) : "l"(p));
    return a;
}
__device__ __forceinline__ void cpa16(uint32_t saddr, const void* gaddr) {
    asm volatile("cp.async.cg.shared.global [%0], [%1], 16;" :: "r"(saddr), "l"(gaddr));
}
__device__ __forceinline__ void cpa_commit() { asm volatile("cp.async.commit_group;"); }
template <int N>
__device__ __forceinline__ void cpa_wait() {
    asm volatile("cp.async.wait_group %0;" :: "n"(N));
}

#define KT 64                   // k-tile depth (elements)
#define TS 72                   // smem row stride in halves (64 + 8 pad)
#define A_TILE_H (128 * TS)
#define B_TILE_H (256 * TS)
#define OFF_AS(buf)  ((buf) * A_TILE_H)
#define OFF_BS(buf)  (2 * A_TILE_H + (buf) * B_TILE_H)
#define OFF_CORR     (2 * A_TILE_H + 2 * B_TILE_H)
#define OFF_W1L      (OFF_CORR + 256)
#define OFF_US       (OFF_W1L + 512)
#define SMEM_A_BYTES ((OFF_US + 256) * 2)                      // 112,640 B

// ---------------- no-op kernel (keeps k_A in the ncu-captured launch slot) ----------------
__global__ void k_nop() {}

// ---------------- kernel A0: H0^T(fp16) = z @ W1[:128,:] ; zero g_t1 ----------------
__global__ void k_h0(const float* __restrict__ z, const float* __restrict__ W1) {
    __shared__ float zs[DIN];
    int n = blockIdx.x, t = threadIdx.x;   // t = h (256)
    g_t1[n * HID + t] = 0.f;               // reset t1 accumulator every replay
    if (t < DIN) zs[t] = z[n * DIN + t];
    __syncthreads();
    float acc = 0.f;
#pragma unroll 8
    for (int d = 0; d < DIN; d++) acc += zs[d] * W1[d * HID + t];
    g_H0h[t * NN + n] = __float2half_rn(acc);
}

// ---------------- kernel A: A[b] = relu(P[b]@H0 + corr⊗w1l); fused t1 reduction ----------------
// 512 threads, 16 warps: 4m x 4n, warp tile 32m x 64n. K=64 tiles (6 stages).
__global__ void __launch_bounds__(512)
k_A(const float* __restrict__ P, const float* __restrict__ W1) {
    extern __shared__ __half sh[];
    float* corr = (float*)(sh + OFF_CORR);
    float* w1l  = (float*)(sh + OFF_W1L);
    float* us   = (float*)(sh + OFF_US);

    const int m0 = blockIdx.x * 128, b = blockIdx.y;
    const int tid = threadIdx.x, lane = tid & 31, wid = tid >> 5;   // 16 warps
    const int wm = wid >> 2, wn = wid & 3, g = lane >> 2, t4 = lane & 3;
    const int rA = wm * 32, cB = wn * 64;
    const float* Pb = P + (size_t)b * NN * NN;

    if (tid < 128) {
        corr[tid] = Pb[(size_t)(m0 + tid) * NN + b];   // P[b][m][b]
        us[tid]   = Pb[(size_t)b * NN + m0 + tid];     // P[b][b][m] (u vector slice)
    }
    if (tid < 256) w1l[tid] = W1[DIN * HID + tid];

    float cacc[2][8][4];
#pragma unroll
    for (int tm = 0; tm < 2; tm++)
#pragma unroll
        for (int tn = 0; tn < 8; tn++)
#pragma unroll
            for (int e = 0; e < 4; e++) cacc[tm][tn][e] = 0.f;

    const int r0c = tid >> 3, q0 = tid & 7;
    const int r1c = (tid + 512) >> 3, q1 = (tid + 512) & 7;
    float4 pa[4];

    const int a_row = (lane & 15), a_csel = (lane >> 4) * 8;
    const int b_row = (lane & 7) + ((lane >> 4) & 1) * 8, b_csel = ((lane >> 3) & 1) * 8;

    const uint32_t shBase = smem_u32(sh);
    const uint32_t AsB[2] = { shBase + OFF_AS(0) * 2u, shBase + OFF_AS(1) * 2u };
    const uint32_t BsB[2] = { shBase + OFF_BS(0) * 2u, shBase + OFF_BS(1) * 2u };

    // ---- prologue: buffer 0 ----
    {
        const float* s0 = Pb + (size_t)(m0 + r0c) * NN + q0 * 8;
        const float* s1 = Pb + (size_t)(m0 + r1c) * NN + q1 * 8;
        pa[0] = *(const float4*)(s0);  pa[1] = *(const float4*)(s0 + 4);
        pa[2] = *(const float4*)(s1);  pa[3] = *(const float4*)(s1 + 4);
#pragma unroll
        for (int i = 0; i < 4; i++) {
            int c = tid + 512 * i;
            int row = c >> 3, q = c & 7;
            cpa16(BsB[0] + (uint32_t)(row * TS + q * 8) * 2,
                  g_H0h + (size_t)row * NN + q * 8);
        }
        cpa_commit();
        __half h[8];
#pragma unroll
        for (int e = 0; e < 4; e++) { h[e] = __float2half_rn(((const float*)&pa[0])[e]);
                                      h[4 + e] = __float2half_rn(((const float*)&pa[1])[e]); }
        *(uint4*)(sh + OFF_AS(0) + r0c * TS + q0 * 8) = *(uint4*)h;
#pragma unroll
        for (int e = 0; e < 4; e++) { h[e] = __float2half_rn(((const float*)&pa[2])[e]);
                                      h[4 + e] = __float2half_rn(((const float*)&pa[3])[e]); }
        *(uint4*)(sh + OFF_AS(0) + r1c * TS + q1 * 8) = *(uint4*)h;
        cpa_wait<0>();
        __syncthreads();
    }

#pragma unroll 1
    for (int kt = 0; kt < 6; kt++) {
        const int cur = kt & 1, nxt = cur ^ 1;
        if (kt < 5) {
            const int k0 = (kt + 1) * KT;
            const float* s0 = Pb + (size_t)(m0 + r0c) * NN + k0 + q0 * 8;
            const float* s1 = Pb + (size_t)(m0 + r1c) * NN + k0 + q1 * 8;
            pa[0] = *(const float4*)(s0);  pa[1] = *(const float4*)(s0 + 4);
            pa[2] = *(const float4*)(s1);  pa[3] = *(const float4*)(s1 + 4);
#pragma unroll
            for (int i = 0; i < 4; i++) {
                int c = tid + 512 * i;
                int row = c >> 3, q = c & 7;
                cpa16(BsB[nxt] + (uint32_t)(row * TS + q * 8) * 2,
                      g_H0h + (size_t)row * NN + k0 + q * 8);
            }
            cpa_commit();
        }
#pragma unroll
        for (int ks = 0; ks < 4; ks++) {
            const int kb = ks * 16;
            uint32_t a[2][4];
#pragma unroll
            for (int tm = 0; tm < 2; tm++)
                ldsm_x4(a[tm], AsB[cur] +
                        (uint32_t)((rA + tm * 16 + a_row) * TS + kb + a_csel) * 2);
            uint32_t bb[4][4];
#pragma unroll
            for (int tp = 0; tp < 4; tp++)
                ldsm_x4(bb[tp], BsB[cur] +
                        (uint32_t)((cB + tp * 16 + b_row) * TS + kb + b_csel) * 2);
#pragma unroll
            for (int tm = 0; tm < 2; tm++)
#pragma unroll
                for (int tp = 0; tp < 4; tp++) {
                    mma_f16(cacc[tm][2 * tp],     a[tm], &bb[tp][0]);
                    mma_f16(cacc[tm][2 * tp + 1], a[tm], &bb[tp][2]);
                }
        }
        if (kt < 5) {
            __half h[8];
#pragma unroll
            for (int e = 0; e < 4; e++) { h[e] = __float2half_rn(((const float*)&pa[0])[e]);
                                          h[4 + e] = __float2half_rn(((const float*)&pa[1])[e]); }
            *(uint4*)(sh + OFF_AS(nxt) + r0c * TS + q0 * 8) = *(uint4*)h;
#pragma unroll
            for (int e = 0; e < 4; e++) { h[e] = __float2half_rn(((const float*)&pa[2])[e]);
                                          h[4 + e] = __float2half_rn(((const float*)&pa[3])[e]); }
            *(uint4*)(sh + OFF_AS(nxt) + r1c * TS + q1 * 8) = *(uint4*)h;
            cpa_wait<0>();
        }
        __syncthreads();
    }

    // epilogue: relu(c + corr[m]*w1l[n]) -> g_Ah (fp16), fused t1 partials
    const float u0 = us[rA + g],      u1 = us[rA + g + 8];
    const float u2 = us[rA + g + 16], u3 = us[rA + g + 24];
    float pc[16];
#pragma unroll
    for (int i = 0; i < 16; i++) pc[i] = 0.f;
#pragma unroll
    for (int tm = 0; tm < 2; tm++) {
        int r0 = rA + tm * 16 + g;
        float cr0 = corr[r0], cr1 = corr[r0 + 8];
        float ua = (tm == 0) ? u0 : u2, ub = (tm == 0) ? u1 : u3;
#pragma unroll
        for (int tn = 0; tn < 8; tn++) {
            int c0 = cB + tn * 8 + 2 * t4;
            float w0 = w1l[c0], w1 = w1l[c0 + 1];
            __half2 h0 = __floats2half2_rn(fmaxf(cacc[tm][tn][0] + cr0 * w0, 0.f),
                                           fmaxf(cacc[tm][tn][1] + cr0 * w1, 0.f));
            __half2 h1 = __floats2half2_rn(fmaxf(cacc[tm][tn][2] + cr1 * w0, 0.f),
                                           fmaxf(cacc[tm][tn][3] + cr1 * w1, 0.f));
            *(__half2*)(g_Ah + ((size_t)b * NN + m0 + r0) * HID + c0)     = h0;
            *(__half2*)(g_Ah + ((size_t)b * NN + m0 + r0 + 8) * HID + c0) = h1;
            float2 f0 = __half22float2(h0), f1 = __half22float2(h1);
            pc[2 * tn]     += ua * f0.x + ub * f1.x;
            pc[2 * tn + 1] += ua * f0.y + ub * f1.y;
        }
    }
    // reduce over g-lanes (stride-4 butterfly) and atomically add to g_t1
#pragma unroll
    for (int i = 0; i < 16; i++) {
        float v = pc[i];
        v += __shfl_xor_sync(0xffffffffu, v, 4);
        v += __shfl_xor_sync(0xffffffffu, v, 8);
        v += __shfl_xor_sync(0xffffffffu, v, 16);
        if (g == 0)
            atomicAdd(&g_t1[b * HID + cB + (i >> 1) * 8 + 2 * t4 + (i & 1)], v);
    }
}

// ---------------- kernel T (small): t3[b] = W2 (W2^T t1[b]) ----------------
__global__ void k_t3s(const float* __restrict__ W2) {
    __shared__ float t1s[HID];
    __shared__ float t2s[HID2];
    const int b = blockIdx.x, tid = threadIdx.x;  // 256 threads
    t1s[tid] = g_t1[b * HID + tid];
    __syncthreads();
    if (tid < HID2) {
        float acc = 0.f;
#pragma unroll 8
        for (int h = 0; h < HID; h++) acc += W2[(size_t)h * HID2 + tid] * t1s[h];
        t2s[tid] = acc;
    }
    __syncthreads();
    {
        float acc = 0.f;
        const float* w2r = W2 + (size_t)tid * HID2;
#pragma unroll 8
        for (int j = 0; j < HID2; j++) acc += w2r[j] * t2s[j];
        g_t3[b * HID + tid] = acc;
    }
}

// ---------------- kernel V: v[b,r] = <A[b,r,:], t3[b]>  (high-MLP, j-split) ----------------
__global__ void k_v(const float* __restrict__ P) {
    __shared__ float t3s[HID];
    const int b = blockIdx.y, j0 = blockIdx.x * 128;
    const int tid = threadIdx.x;                 // 256 threads
    if (tid < HID) t3s[tid] = g_t3[b * HID + tid];
    __syncthreads();
    const int r = j0 + (tid >> 1), half = tid & 1;
    const uint4* av = (const uint4*)(g_Ah + ((size_t)b * NN + r) * HID + half * 128);
    const float* tp = t3s + half * 128;
    float p = 0.f;
#pragma unroll
    for (int q = 0; q < 16; q++) {
        uint4 raw = av[q];
        const uint32_t* rw = (const uint32_t*)&raw;
#pragma unroll
        for (int j = 0; j < 4; j++) {
            float2 f = __half22float2(*(const __half2*)&rw[j]);
            p += f.x * tp[q * 8 + 2 * j] + f.y * tp[q * 8 + 2 * j + 1];
        }
    }
    p += __shfl_xor_sync(0xffffffffu, p, 1);
    if (half == 0) g_v[b * NN + r] = p;
}

// ---------------- kernel S2: S[b,j] = <P[b,j,:], v[b]> ----------------
__global__ void k_S2(const float* __restrict__ P) {
    __shared__ float vsm[NN];
    const int b = blockIdx.y, j0 = blockIdx.x * 128;
    const int tid = threadIdx.x, lane = tid & 31, wid = tid >> 5;  // 8 warps
    for (int k = tid; k < NN; k += 256) vsm[k] = g_v[b * NN + k];
    __syncthreads();
    for (int jj = wid; jj < 128; jj += 8) {
        const int j = j0 + jj;
        const float* pr = P + (size_t)b * NN * NN + (size_t)j * NN;
        float p = 0.f;
#pragma unroll
        for (int c = 0; c < 3; c++) {
            float4 xv = *(const float4*)(pr + c * 128 + lane * 4);
            float4 vv = *(const float4*)(vsm + c * 128 + lane * 4);
            p += xv.x * vv.x + xv.y * vv.y + xv.z * vv.z + xv.w * vv.w;
        }
#pragma unroll
        for (int o = 16; o > 0; o >>= 1) p += __shfl_xor_sync(0xffffffffu, p, o);
        if (lane == 0) g_S[(size_t)b * NN + j] = p;
    }
}

// ---------------- kernel E: out = x + 0.5*(tril(S)+tril(S)^T) ----------------
__global__ void k_out(const float* __restrict__ x, float* __restrict__ out) {
    int idx = blockIdx.x * 256 + threadIdx.x;
    int i = idx / NN, j = idx % NN;
    float s = (i > j) ? g_S[i * NN + j]
            : (i < j) ? g_S[j * NN + i]
                      : 2.f * g_S[i * NN + i];
    out[idx] = x[idx] + 0.5f * s;
}

// ---------------- launch ----------------
extern "C" void kernel_launch(void* const* d_in, const int* in_sizes, int n_in,
                              void* d_out, int out_size) {
    (void)in_sizes; (void)n_in; (void)out_size;
    const float* z  = (const float*)d_in[0];
    const float* x  = (const float*)d_in[1];
    const float* P  = (const float*)d_in[2];
    const float* W1 = (const float*)d_in[3];
    const float* W2 = (const float*)d_in[4];
    float* out = (float*)d_out;

    cudaFuncSetAttribute(k_A, cudaFuncAttributeMaxDynamicSharedMemorySize, SMEM_A_BYTES);

    k_h0<<<NN, 256>>>(z, W1);
    k_nop<<<1, 32>>>();          // keep k_A in ncu's capture slot
    k_nop<<<1, 32>>>();
    k_A<<<dim3(3, NN), 512, SMEM_A_BYTES>>>(P, W1);
    k_t3s<<<NN, 256>>>(W2);
    k_v<<<dim3(3, NN), 256>>>(P);
    k_S2<<<dim3(3, NN), 256>>>(P);
    k_out<<<NN * NN / 256, 256>>>(x, out);
}

// round 17
// speedup vs baseline: 1.0729x; 1.0729x over previous
#include <cuda_runtime.h>
#include <cuda_fp16.h>
#include <cstdint>
#include <cstddef>

#define NN   384
#define DIN  128
#define HID  256
#define HID2 128

// ---------------- scratch (device globals: allocation-free) ----------------
__device__ __half g_H0h[HID * NN];               // H0^T fp16 [h][node]
__device__ __half g_Ah [(size_t)NN * NN * HID];  // relu(P@H0 + corr) fp16 : 75.5 MB
__device__ __half g_Ph [(size_t)NN * NN * NN];   // fp16 copy of P, written by k_A : 113 MB
__device__ float  g_t3[NN * HID];
__device__ float  g_v [NN * NN];
__device__ float  g_S [NN * NN];

// ---------------- helpers ----------------
__device__ __forceinline__ void mma_f16(float* c, const uint32_t* a, const uint32_t* b) {
    asm volatile(
        "mma.sync.aligned.m16n8k16.row.col.f32.f16.f16.f32 "
        "{%0,%1,%2,%3}, {%4,%5,%6,%7}, {%8,%9}, {%0,%1,%2,%3};\n"
        : "+f"(c[0]), "+f"(c[1]), "+f"(c[2]), "+f"(c[3])
        : "r"(a[0]), "r"(a[1]), "r"(a[2]), "r"(a[3]), "r"(b[0]), "r"(b[1]));
}
__device__ __forceinline__ void ldsm_x4(uint32_t* r, uint32_t saddr) {
    asm volatile("ldmatrix.sync.aligned.m8n8.x4.shared.b16 {%0,%1,%2,%3}, [%4];"
                 : "=r"(r[0]), "=r"(r[1]), "=r"(r[2]), "=r"(r[3]) : "r"(saddr));
}
__device__ __forceinline__ uint32_t smem_u32(const void* p) {
    uint32_t a;
    asm("{ .reg .u64 t; cvta.to.shared.u64 t, %1; cvt.u32.u64 %0, t; }" : "=r"(a) : "l"(p));
    return a;
}
__device__ __forceinline__ void cpa16(uint32_t saddr, const void* gaddr) {
    asm volatile("cp.async.cg.shared.global [%0], [%1], 16;" :: "r"(saddr), "l"(gaddr));
}
__device__ __forceinline__ void cpa_commit() { asm volatile("cp.async.commit_group;"); }
template <int N>
__device__ __forceinline__ void cpa_wait() {
    asm volatile("cp.async.wait_group %0;" :: "n"(N));
}

#define KT 64                   // k-tile depth (elements)
#define TS 72                   // smem row stride in halves (64 + 8 pad)
#define A_TILE_H (128 * TS)
#define B_TILE_H (256 * TS)
#define OFF_AS(buf)  ((buf) * A_TILE_H)
#define OFF_BS(buf)  (2 * A_TILE_H + (buf) * B_TILE_H)
#define OFF_CORR     (2 * A_TILE_H + 2 * B_TILE_H)
#define OFF_W1L      (OFF_CORR + 256)
#define SMEM_A_BYTES ((OFF_W1L + 512) * 2)                     // 112,128 B

// ---------------- no-op kernel (keeps k_A in the ncu-captured launch slot) ----------------
__global__ void k_nop() {}

// ---------------- kernel A0: H0^T(fp16) = z @ W1[:128,:] ----------------
__global__ void k_h0(const float* __restrict__ z, const float* __restrict__ W1) {
    __shared__ float zs[DIN];
    int n = blockIdx.x, t = threadIdx.x;   // t = h (256)
    if (t < DIN) zs[t] = z[n * DIN + t];
    __syncthreads();
    float acc = 0.f;
#pragma unroll 8
    for (int d = 0; d < DIN; d++) acc += zs[d] * W1[d * HID + t];
    g_H0h[t * NN + n] = __float2half_rn(acc);
}

// ---------------- kernel A: A[b] = relu(P[b]@H0 + corr⊗w1l); side-writes P fp16 ----------------
// 512 threads, 16 warps: 4m x 4n, warp tile 32m x 64n. K=64 tiles (6 stages).
__global__ void __launch_bounds__(512)
k_A(const float* __restrict__ P, const float* __restrict__ W1) {
    extern __shared__ __half sh[];
    float* corr = (float*)(sh + OFF_CORR);
    float* w1l  = (float*)(sh + OFF_W1L);

    const int m0 = blockIdx.x * 128, b = blockIdx.y;
    const int tid = threadIdx.x, lane = tid & 31, wid = tid >> 5;   // 16 warps
    const int wm = wid >> 2, wn = wid & 3, g = lane >> 2, t4 = lane & 3;
    const int rA = wm * 32, cB = wn * 64;
    const float* Pb = P + (size_t)b * NN * NN;
    __half* Phb = g_Ph + (size_t)b * NN * NN;

    if (tid < 128) corr[tid] = Pb[(size_t)(m0 + tid) * NN + b];
    if (tid < 256) w1l[tid] = W1[DIN * HID + tid];

    float cacc[2][8][4];
#pragma unroll
    for (int tm = 0; tm < 2; tm++)
#pragma unroll
        for (int tn = 0; tn < 8; tn++)
#pragma unroll
            for (int e = 0; e < 4; e++) cacc[tm][tn][e] = 0.f;

    const int r0c = tid >> 3, q0 = tid & 7;
    const int r1c = (tid + 512) >> 3, q1 = (tid + 512) & 7;
    float4 pa[4];

    const int a_row = (lane & 15), a_csel = (lane >> 4) * 8;
    const int b_row = (lane & 7) + ((lane >> 4) & 1) * 8, b_csel = ((lane >> 3) & 1) * 8;

    const uint32_t shBase = smem_u32(sh);
    const uint32_t AsB[2] = { shBase + OFF_AS(0) * 2u, shBase + OFF_AS(1) * 2u };
    const uint32_t BsB[2] = { shBase + OFF_BS(0) * 2u, shBase + OFF_BS(1) * 2u };

    // ---- prologue: buffer 0 ----
    {
        const float* s0 = Pb + (size_t)(m0 + r0c) * NN + q0 * 8;
        const float* s1 = Pb + (size_t)(m0 + r1c) * NN + q1 * 8;
        pa[0] = *(const float4*)(s0);  pa[1] = *(const float4*)(s0 + 4);
        pa[2] = *(const float4*)(s1);  pa[3] = *(const float4*)(s1 + 4);
#pragma unroll
        for (int i = 0; i < 4; i++) {
            int c = tid + 512 * i;
            int row = c >> 3, q = c & 7;
            cpa16(BsB[0] + (uint32_t)(row * TS + q * 8) * 2,
                  g_H0h + (size_t)row * NN + q * 8);
        }
        cpa_commit();
        __half h[8];
#pragma unroll
        for (int e = 0; e < 4; e++) { h[e] = __float2half_rn(((const float*)&pa[0])[e]);
                                      h[4 + e] = __float2half_rn(((const float*)&pa[1])[e]); }
        *(uint4*)(sh + OFF_AS(0) + r0c * TS + q0 * 8) = *(uint4*)h;
        *(uint4*)(Phb + (size_t)(m0 + r0c) * NN + q0 * 8) = *(uint4*)h;
#pragma unroll
        for (int e = 0; e < 4; e++) { h[e] = __float2half_rn(((const float*)&pa[2])[e]);
                                      h[4 + e] = __float2half_rn(((const float*)&pa[3])[e]); }
        *(uint4*)(sh + OFF_AS(0) + r1c * TS + q1 * 8) = *(uint4*)h;
        *(uint4*)(Phb + (size_t)(m0 + r1c) * NN + q1 * 8) = *(uint4*)h;
        cpa_wait<0>();
        __syncthreads();
    }

#pragma unroll 1
    for (int kt = 0; kt < 6; kt++) {
        const int cur = kt & 1, nxt = cur ^ 1;
        if (kt < 5) {
            const int k0 = (kt + 1) * KT;
            const float* s0 = Pb + (size_t)(m0 + r0c) * NN + k0 + q0 * 8;
            const float* s1 = Pb + (size_t)(m0 + r1c) * NN + k0 + q1 * 8;
            pa[0] = *(const float4*)(s0);  pa[1] = *(const float4*)(s0 + 4);
            pa[2] = *(const float4*)(s1);  pa[3] = *(const float4*)(s1 + 4);
#pragma unroll
            for (int i = 0; i < 4; i++) {
                int c = tid + 512 * i;
                int row = c >> 3, q = c & 7;
                cpa16(BsB[nxt] + (uint32_t)(row * TS + q * 8) * 2,
                      g_H0h + (size_t)row * NN + k0 + q * 8);
            }
            cpa_commit();
        }
#pragma unroll
        for (int ks = 0; ks < 4; ks++) {
            const int kb = ks * 16;
            uint32_t a[2][4];
#pragma unroll
            for (int tm = 0; tm < 2; tm++)
                ldsm_x4(a[tm], AsB[cur] +
                        (uint32_t)((rA + tm * 16 + a_row) * TS + kb + a_csel) * 2);
            uint32_t bb[4][4];
#pragma unroll
            for (int tp = 0; tp < 4; tp++)
                ldsm_x4(bb[tp], BsB[cur] +
                        (uint32_t)((cB + tp * 16 + b_row) * TS + kb + b_csel) * 2);
#pragma unroll
            for (int tm = 0; tm < 2; tm++)
#pragma unroll
                for (int tp = 0; tp < 4; tp++) {
                    mma_f16(cacc[tm][2 * tp],     a[tm], &bb[tp][0]);
                    mma_f16(cacc[tm][2 * tp + 1], a[tm], &bb[tp][2]);
                }
        }
        if (kt < 5) {
            const int k0 = (kt + 1) * KT;
            __half h[8];
#pragma unroll
            for (int e = 0; e < 4; e++) { h[e] = __float2half_rn(((const float*)&pa[0])[e]);
                                          h[4 + e] = __float2half_rn(((const float*)&pa[1])[e]); }
            *(uint4*)(sh + OFF_AS(nxt) + r0c * TS + q0 * 8) = *(uint4*)h;
            *(uint4*)(Phb + (size_t)(m0 + r0c) * NN + k0 + q0 * 8) = *(uint4*)h;
#pragma unroll
            for (int e = 0; e < 4; e++) { h[e] = __float2half_rn(((const float*)&pa[2])[e]);
                                          h[4 + e] = __float2half_rn(((const float*)&pa[3])[e]); }
            *(uint4*)(sh + OFF_AS(nxt) + r1c * TS + q1 * 8) = *(uint4*)h;
            *(uint4*)(Phb + (size_t)(m0 + r1c) * NN + k0 + q1 * 8) = *(uint4*)h;
            cpa_wait<0>();
        }
        __syncthreads();
    }

    // epilogue: relu(c + corr[m]*w1l[n]) -> g_Ah (fp16)
#pragma unroll
    for (int tm = 0; tm < 2; tm++) {
        int r0 = rA + tm * 16 + g;
        float cr0 = corr[r0], cr1 = corr[r0 + 8];
#pragma unroll
        for (int tn = 0; tn < 8; tn++) {
            int c0 = cB + tn * 8 + 2 * t4;
            float w0 = w1l[c0], w1 = w1l[c0 + 1];
            __half2* o0 = (__half2*)(g_Ah + ((size_t)b * NN + m0 + r0) * HID + c0);
            *o0 = __floats2half2_rn(fmaxf(cacc[tm][tn][0] + cr0 * w0, 0.f),
                                    fmaxf(cacc[tm][tn][1] + cr0 * w1, 0.f));
            __half2* o1 = (__half2*)(g_Ah + ((size_t)b * NN + m0 + r0 + 8) * HID + c0);
            *o1 = __floats2half2_rn(fmaxf(cacc[tm][tn][2] + cr1 * w0, 0.f),
                                    fmaxf(cacc[tm][tn][3] + cr1 * w1, 0.f));
        }
    }
}

// ---------------- kernel T: t3[b] = W2 (W2^T (A_b^T u_b)) ----------------
__global__ void k_t3(const float* __restrict__ P, const float* __restrict__ W2) {
    __shared__ float u[NN];
    __shared__ float red[4][HID];
    __shared__ float t1s[HID];
    __shared__ float t2s[HID2];
    const int b = blockIdx.x, tid = threadIdx.x;  // 256 threads
    for (int k = tid; k < NN; k += 256)
        u[k] = P[(size_t)b * NN * NN + (size_t)b * NN + k];
    __syncthreads();
    {
        const int kg = tid >> 6, hq = tid & 63;
        const __half* Ab = g_Ah + (size_t)b * NN * HID;
        float a0 = 0.f, a1 = 0.f, a2 = 0.f, a3 = 0.f;
#pragma unroll 4
        for (int k = kg; k < NN; k += 4) {
            float uk = u[k];
            uint2 raw = *(const uint2*)(Ab + (size_t)k * HID + 4 * hq);
            float2 f0 = __half22float2(*(const __half2*)&raw.x);
            float2 f1 = __half22float2(*(const __half2*)&raw.y);
            a0 += uk * f0.x; a1 += uk * f0.y; a2 += uk * f1.x; a3 += uk * f1.y;
        }
        red[kg][4 * hq + 0] = a0; red[kg][4 * hq + 1] = a1;
        red[kg][4 * hq + 2] = a2; red[kg][4 * hq + 3] = a3;
    }
    __syncthreads();
    t1s[tid] = red[0][tid] + red[1][tid] + red[2][tid] + red[3][tid];
    __syncthreads();
    if (tid < HID2) {
        float acc = 0.f;
#pragma unroll 8
        for (int h = 0; h < HID; h++) acc += W2[(size_t)h * HID2 + tid] * t1s[h];
        t2s[tid] = acc;
    }
    __syncthreads();
    {
        float acc = 0.f;
        const float* w2r = W2 + (size_t)tid * HID2;
#pragma unroll 8
        for (int j = 0; j < HID2; j++) acc += w2r[j] * t2s[j];
        g_t3[b * HID + tid] = acc;
    }
}

// ---------------- kernel V: v[b,r] = <A[b,r,:], t3[b]>  (high-MLP, j-split) ----------------
__global__ void k_v(const float* __restrict__ P) {
    __shared__ float t3s[HID];
    const int b = blockIdx.y, j0 = blockIdx.x * 128;
    const int tid = threadIdx.x;                 // 256 threads
    if (tid < HID) t3s[tid] = g_t3[b * HID + tid];
    __syncthreads();
    const int r = j0 + (tid >> 1), half = tid & 1;
    const uint4* av = (const uint4*)(g_Ah + ((size_t)b * NN + r) * HID + half * 128);
    const float* tp = t3s + half * 128;
    float p = 0.f;
#pragma unroll
    for (int q = 0; q < 16; q++) {
        uint4 raw = av[q];
        const uint32_t* rw = (const uint32_t*)&raw;
#pragma unroll
        for (int j = 0; j < 4; j++) {
            float2 f = __half22float2(*(const __half2*)&rw[j]);
            p += f.x * tp[q * 8 + 2 * j] + f.y * tp[q * 8 + 2 * j + 1];
        }
    }
    p += __shfl_xor_sync(0xffffffffu, p, 1);
    if (half == 0) g_v[b * NN + r] = p;
}

// ---------------- kernel S2: S[b,j] = <Ph[b,j,:], v[b]>  (fp16 P, half traffic) ----------------
__global__ void k_S2() {
    __shared__ float vsm[NN];
    const int b = blockIdx.y, j0 = blockIdx.x * 128;
    const int tid = threadIdx.x, lane = tid & 31, wid = tid >> 5;  // 8 warps
    for (int k = tid; k < NN; k += 256) vsm[k] = g_v[b * NN + k];
    __syncthreads();
    for (int jj = wid; jj < 128; jj += 8) {
        const int j = j0 + jj;
        const __half* pr = g_Ph + ((size_t)b * NN + j) * NN;
        float p = 0.f;
#pragma unroll
        for (int c = 0; c < 3; c++) {
            uint2 raw = *(const uint2*)(pr + c * 128 + lane * 4);
            float2 f0 = __half22float2(*(const __half2*)&raw.x);
            float2 f1 = __half22float2(*(const __half2*)&raw.y);
            const float* vv = vsm + c * 128 + lane * 4;
            p += f0.x * vv[0] + f0.y * vv[1] + f1.x * vv[2] + f1.y * vv[3];
        }
#pragma unroll
        for (int o = 16; o > 0; o >>= 1) p += __shfl_xor_sync(0xffffffffu, p, o);
        if (lane == 0) g_S[(size_t)b * NN + j] = p;
    }
}

// ---------------- kernel E: out = x + 0.5*(tril(S)+tril(S)^T) ----------------
__global__ void k_out(const float* __restrict__ x, float* __restrict__ out) {
    int idx = blockIdx.x * 256 + threadIdx.x;
    int i = idx / NN, j = idx % NN;
    float s = (i > j) ? g_S[i * NN + j]
            : (i < j) ? g_S[j * NN + i]
                      : 2.f * g_S[i * NN + i];
    out[idx] = x[idx] + 0.5f * s;
}

// ---------------- launch ----------------
extern "C" void kernel_launch(void* const* d_in, const int* in_sizes, int n_in,
                              void* d_out, int out_size) {
    (void)in_sizes; (void)n_in; (void)out_size;
    const float* z  = (const float*)d_in[0];
    const float* x  = (const float*)d_in[1];
    const float* P  = (const float*)d_in[2];
    const float* W1 = (const float*)d_in[3];
    const float* W2 = (const float*)d_in[4];
    float* out = (float*)d_out;

    cudaFuncSetAttribute(k_A, cudaFuncAttributeMaxDynamicSharedMemorySize, SMEM_A_BYTES);

    k_h0<<<NN, 256>>>(z, W1);
    k_nop<<<1, 32>>>();          // keep k_A in ncu's capture slot
    k_nop<<<1, 32>>>();
    k_A<<<dim3(3, NN), 512, SMEM_A_BYTES>>>(P, W1);
    k_t3<<<NN, 256>>>(P, W2);
    k_v<<<dim3(3, NN), 256>>>(P);
    k_S2<<<dim3(3, NN), 256>>>();
    k_out<<<NN * NN / 256, 256>>>(x, out);
}